// round 14
// baseline (speedup 1.0000x reference)
#include <cuda_runtime.h>
#include <cuda_bf16.h>
#include <cstdint>

#define BB 16
#define TT 1024
#define DD 512

// ---------------- device scratch (no allocation allowed) -------------------
__device__ __align__(16) uint8_t g_f8[BB * TT * DD];   // 8 MB normalized e4m3 (x32 scale)
__device__ float g_S48[48][BB * TT];   // 0..31 row-slots (j*4+wn), 32..47 col-slots (32+i*2+wm)
__device__ float g_pos[BB * TT];       // sim[t, t+1]

// Symmetric 128x128 tile schedule: 36 tiles/batch. code = i | (j<<4) | (full<<8)
__constant__ int c_tiles[36] = {
    0x000, 0x011, 0x022, 0x033, 0x044, 0x055, 0x066, 0x077,   // diagonal
    0x110,
    0x120, 0x121,
    0x130, 0x131, 0x132,
    0x140, 0x141, 0x142, 0x143,
    0x150, 0x151, 0x152, 0x153, 0x154,
    0x160, 0x161, 0x162, 0x163, 0x164, 0x165,
    0x170, 0x171, 0x172, 0x173, 0x174, 0x175, 0x176
};

// ---------------- PTX helpers ----------------------------------------------
__device__ __forceinline__ uint32_t smem_u32(const void* p) {
    uint32_t a;
    asm("{ .reg .u64 t; cvta.to.shared.u64 t, %1; cvt.u32.u64 %0, t; }"
        : "=r"(a) : "l"(p));
    return a;
}
__device__ __forceinline__ void cp16(uint32_t dst, const void* src) {
    asm volatile("cp.async.cg.shared.global [%0], [%1], 16;"
                 :: "r"(dst), "l"(src) : "memory");
}
__device__ __forceinline__ void ldsm4(uint32_t r[4], uint32_t addr) {
    asm volatile("ldmatrix.sync.aligned.m8n8.x4.shared.b16 {%0,%1,%2,%3}, [%4];"
                 : "=r"(r[0]), "=r"(r[1]), "=r"(r[2]), "=r"(r[3]) : "r"(addr));
}
// fp8 e4m3 MMA: m16n8k32, fragment layout = bf16 m16n8k16 with b16 -> fp8 pair
__device__ __forceinline__ void mma_fp8(float c[4], uint32_t a0, uint32_t a1,
                                        uint32_t a2, uint32_t a3,
                                        uint32_t b0, uint32_t b1) {
    asm volatile(
        "mma.sync.aligned.m16n8k32.row.col.f32.e4m3.e4m3.f32 "
        "{%0,%1,%2,%3}, {%4,%5,%6,%7}, {%8,%9}, {%0,%1,%2,%3};"
        : "+f"(c[0]), "+f"(c[1]), "+f"(c[2]), "+f"(c[3])
        : "r"(a0), "r"(a1), "r"(a2), "r"(a3), "r"(b0), "r"(b1));
}
// pack 4 floats -> 4 e4m3 bytes (byte i = value i)
__device__ __forceinline__ uint32_t pack_e4m3(float v0, float v1, float v2, float v3) {
    uint16_t lo, hi;
    asm("cvt.rn.satfinite.e4m3x2.f32 %0, %1, %2;" : "=h"(lo) : "f"(v1), "f"(v0));
    asm("cvt.rn.satfinite.e4m3x2.f32 %0, %1, %2;" : "=h"(hi) : "f"(v3), "f"(v2));
    return (uint32_t)lo | ((uint32_t)hi << 16);
}

#define STAGE_BYTES 16384           // A: 128*64B + B: 128*64B
#define NSTAGE 4
#define NCHUNK 8                    // 512 fp8 bytes / 64B per chunk
// conflict-free swizzle: quad(row) = ((row&1)<<2) | (g ^ ((row>>1)&3))
#define SWZ(g, row) (((g) ^ (((row) >> 1) & 3)) * 16)

// ---------------------------------------------------------------------------
// Kernel 1: normalize, emit e4m3 scaled by 32. Two rows per warp.
// ---------------------------------------------------------------------------
__global__ __launch_bounds__(256) void norm_kernel(const float* __restrict__ f) {
    int warp = threadIdx.x >> 5, lane = threadIdx.x & 31;
    int row0 = (blockIdx.x * 8 + warp) * 2;
    float4 v[2][4];
    float ss0 = 0.f, ss1 = 0.f;
#pragma unroll
    for (int q = 0; q < 4; q++) {
        v[0][q] = reinterpret_cast<const float4*>(f + (size_t)row0 * DD)[lane + q * 32];
        v[1][q] = reinterpret_cast<const float4*>(f + (size_t)(row0 + 1) * DD)[lane + q * 32];
        ss0 += v[0][q].x * v[0][q].x + v[0][q].y * v[0][q].y
             + v[0][q].z * v[0][q].z + v[0][q].w * v[0][q].w;
        ss1 += v[1][q].x * v[1][q].x + v[1][q].y * v[1][q].y
             + v[1][q].z * v[1][q].z + v[1][q].w * v[1][q].w;
    }
#pragma unroll
    for (int o = 16; o; o >>= 1) {
        ss0 += __shfl_xor_sync(0xffffffffu, ss0, o);
        ss1 += __shfl_xor_sync(0xffffffffu, ss1, o);
    }
    // x32 scale folded into the inverse norm
    float inv0 = 32.0f / fmaxf(sqrtf(ss0), 1e-8f);
    float inv1 = 32.0f / fmaxf(sqrtf(ss1), 1e-8f);
#pragma unroll
    for (int rr = 0; rr < 2; rr++) {
        float inv = rr ? inv1 : inv0;
#pragma unroll
        for (int q = 0; q < 4; q++) {
            uint32_t p = pack_e4m3(v[rr][q].x * inv, v[rr][q].y * inv,
                                   v[rr][q].z * inv, v[rr][q].w * inv);
            *reinterpret_cast<uint32_t*>(
                &g_f8[(size_t)(row0 + rr) * DD + (lane + q * 32) * 4]) = p;
        }
    }
}

// ---------------------------------------------------------------------------
// Kernel 2: fp8 QMMA Gram, 128x128 symmetric tiles + fused exp epilogue.
// 8 warps as 2(M) x 4(N), warp tile 64x32. Row = 64B per 64-elem chunk.
// ---------------------------------------------------------------------------
__global__ __launch_bounds__(256, 1) void gram_kernel() {
    extern __shared__ __align__(1024) char smem[];
    const uint32_t sbase = smem_u32(smem);
    const int tid = threadIdx.x;
    const int wid = tid >> 5, lane = tid & 31;
    const int warp_m = wid >> 2, warp_n = wid & 3;

    const int code = c_tiles[blockIdx.x];
    const int ti = code & 15;            // row block
    const int tj = (code >> 4) & 15;     // col block
    const int is_full = code >> 8;       // 1 = strictly above diagonal
    const int t0 = ti * 128;
    const int s0 = tj * 128;
    const int b  = blockIdx.y;
    const uint8_t* __restrict__ G = g_f8 + (size_t)b * TT * DD;

    // ---- load-side per-thread slots (16B each): 2 A + 2 B ----
    const char* asrc[2]; uint32_t adst[2];
    const char* bsrc[2]; uint32_t bdst[2];
#pragma unroll
    for (int i = 0; i < 2; i++) {
        int slot = tid + i * 256, row = slot >> 2, g = slot & 3;
        asrc[i] = reinterpret_cast<const char*>(G + (size_t)(t0 + row) * DD) + g * 16;
        adst[i] = row * 64 + SWZ(g, row);
        bsrc[i] = reinterpret_cast<const char*>(G + (size_t)(s0 + row) * DD) + g * 16;
        bdst[i] = 8192 + row * 64 + SWZ(g, row);
    }

    // ---- ldmatrix per-lane offsets (b16-pair view of fp8 rows) ----
    const int a_row = warp_m * 64 + (lane & 15);
    const int ha = lane >> 4;
    uint32_t a_off[2];
#pragma unroll
    for (int ks = 0; ks < 2; ks++)
        a_off[ks] = a_row * 64 + SWZ(ks * 2 + ha, a_row);
    const int n_row = warp_n * 32 + (lane & 7) + ((lane >> 4) << 3);
    const int hb = (lane >> 3) & 1;
    uint32_t b_off[2];
#pragma unroll
    for (int ks = 0; ks < 2; ks++)
        b_off[ks] = 8192 + n_row * 64 + SWZ(ks * 2 + hb, n_row);

    float acc[4][4][4];
#pragma unroll
    for (int mi = 0; mi < 4; mi++)
#pragma unroll
        for (int ni = 0; ni < 4; ni++)
#pragma unroll
            for (int r = 0; r < 4; r++) acc[mi][ni][r] = 0.f;

#define PREFETCH(c) do {                                                \
        uint32_t st_ = sbase + ((c) & (NSTAGE - 1)) * STAGE_BYTES;      \
        size_t ko_ = (size_t)(c) * 64;                                  \
        cp16(st_ + adst[0], asrc[0] + ko_);                             \
        cp16(st_ + adst[1], asrc[1] + ko_);                             \
        cp16(st_ + bdst[0], bsrc[0] + ko_);                             \
        cp16(st_ + bdst[1], bsrc[1] + ko_);                             \
        asm volatile("cp.async.commit_group;" ::: "memory");            \
    } while (0)

    PREFETCH(0);
    PREFETCH(1);
    PREFETCH(2);

#pragma unroll 1
    for (int c = 0; c < NCHUNK; ++c) {
        if (c + 3 <= NCHUNK)
            asm volatile("cp.async.wait_group 2;" ::: "memory");
        else if (c + 2 == NCHUNK)
            asm volatile("cp.async.wait_group 1;" ::: "memory");
        else
            asm volatile("cp.async.wait_group 0;" ::: "memory");
        __syncthreads();

        if (c + 3 < NCHUNK) PREFETCH(c + 3);

        const uint32_t st = sbase + (c & (NSTAGE - 1)) * STAGE_BYTES;
        uint32_t afr[2][4][4], bfr[2][2][4];
#pragma unroll
        for (int ks = 0; ks < 2; ks++) {
#pragma unroll
            for (int mi = 0; mi < 4; mi++) ldsm4(afr[ks][mi], st + a_off[ks] + mi * 1024);
#pragma unroll
            for (int pi = 0; pi < 2; pi++) ldsm4(bfr[ks][pi], st + b_off[ks] + pi * 1024);
        }
#pragma unroll
        for (int ks = 0; ks < 2; ks++)
#pragma unroll
            for (int mi = 0; mi < 4; mi++)
#pragma unroll
                for (int ni = 0; ni < 4; ni++)
                    mma_fp8(acc[mi][ni],
                            afr[ks][mi][0], afr[ks][mi][1],
                            afr[ks][mi][2], afr[ks][mi][3],
                            bfr[ks][ni >> 1][(ni & 1) * 2],
                            bfr[ks][ni >> 1][(ni & 1) * 2 + 1]);
    }

    // ---- epilogue: acc = 1024*cos. exp((cos-1)/T); mask |s-t|<=1 ----
    const int rL = lane >> 2, cL = (lane & 3) * 2;
    const int row_base = t0 + warp_m * 64;
    const int col_base = s0 + warp_n * 32;
    const int posbase = b * TT;
    float rsum[4][2];
    float csum[4][2];
#pragma unroll
    for (int mi = 0; mi < 4; mi++) { rsum[mi][0] = 0.f; rsum[mi][1] = 0.f; }
#pragma unroll
    for (int ni = 0; ni < 4; ni++) { csum[ni][0] = 0.f; csum[ni][1] = 0.f; }

#pragma unroll
    for (int mi = 0; mi < 4; mi++)
#pragma unroll
        for (int ni = 0; ni < 4; ni++)
#pragma unroll
            for (int r = 0; r < 4; r++) {
                int t = row_base + mi * 16 + rL + (r >> 1) * 8;
                int s = col_base + ni * 8 + cL + (r & 1);
                float v = acc[mi][ni][r];               // 1024 * cos
                int dd = s - t;
                if (dd == 1) g_pos[posbase + t] = v * 0.01395089286f; // /(1024*0.07)
                // z = (cos - 1) * log2e / T = v * (20.6099/1024) - 20.6099
                float z = fmaf(v, 0.02012688387f, -20.6099291f);
                float e;
                asm("ex2.approx.ftz.f32 %0, %1;" : "=f"(e) : "f"(z));
                bool keep = (unsigned)(dd + 1) > 2u;
                float em = keep ? e : 0.f;
                rsum[mi][r >> 1] += em;
                csum[ni][r & 1]  += em;
            }

    // row sums: reduce over the 4 lanes sharing each row (lane bits 0,1)
    const int rslot = tj * 4 + warp_n;
#pragma unroll
    for (int mi = 0; mi < 4; mi++)
#pragma unroll
        for (int h = 0; h < 2; h++) {
            float x = rsum[mi][h];
            x += __shfl_xor_sync(0xffffffffu, x, 1);
            x += __shfl_xor_sync(0xffffffffu, x, 2);
            if ((lane & 3) == 0)
                g_S48[rslot][posbase + row_base + mi * 16 + rL + h * 8] = x;
        }

    // col sums (mirror), full tiles only: reduce over lane bits 2,3,4 (rows)
    if (is_full) {
        const int cslot = 32 + ti * 2 + warp_m;
#pragma unroll
        for (int ni = 0; ni < 4; ni++)
#pragma unroll
            for (int p = 0; p < 2; p++) {
                float x = csum[ni][p];
                x += __shfl_xor_sync(0xffffffffu, x, 4);
                x += __shfl_xor_sync(0xffffffffu, x, 8);
                x += __shfl_xor_sync(0xffffffffu, x, 16);
                if ((lane & 28) == 0)
                    g_S48[cslot][posbase + col_base + ni * 8 + (lane & 3) * 2 + p] = x;
            }
    }
}

// ---------------------------------------------------------------------------
// Kernel 3: combine 48 partials, per-anchor loss, deterministic reduction.
// ---------------------------------------------------------------------------
__global__ __launch_bounds__(1024) void finalize_kernel(float* __restrict__ out) {
    const float M = 14.285714285714286f;   // 1/0.07
    int tid = threadIdx.x;
    float acc = 0.f;
    for (int idx = tid; idx < BB * TT; idx += 1024) {
        int tt = idx & (TT - 1);
        if (tt == 0 || tt == TT - 1) continue;
        float S = 0.f;
#pragma unroll
        for (int p = 0; p < 48; p++) S += g_S48[p][idx];
        float pos = g_pos[idx];
        acc += logf(expf(pos - M) + S) + M - pos;
    }
    __shared__ float sm[1024];
    sm[tid] = acc;
    __syncthreads();
    for (int o = 512; o; o >>= 1) {
        if (tid < o) sm[tid] += sm[tid + o];
        __syncthreads();
    }
    if (tid == 0) out[0] = sm[0] / (float)(BB * (TT - 2));
}

// ---------------------------------------------------------------------------
extern "C" void kernel_launch(void* const* d_in, const int* in_sizes, int n_in,
                              void* d_out, int out_size) {
    const float* features = (const float*)d_in[0];
    float* out = (float*)d_out;

    cudaFuncSetAttribute(gram_kernel,
                         cudaFuncAttributeMaxDynamicSharedMemorySize,
                         NSTAGE * STAGE_BYTES);

    norm_kernel<<<BB * TT / 16, 256>>>(features);
    gram_kernel<<<dim3(36, BB), 256, NSTAGE * STAGE_BYTES>>>();
    finalize_kernel<<<1, 1024>>>(out);
}

// round 15
// speedup vs baseline: 1.2222x; 1.2222x over previous
#include <cuda_runtime.h>
#include <cuda_bf16.h>
#include <cstdint>

#define BB 16
#define TT 1024
#define DD 512

// ---------------- device scratch (no allocation allowed) -------------------
__device__ __align__(16) __nv_bfloat16 g_bf[BB * TT * DD];   // 16 MB normalized bf16
__device__ float g_S48[48][BB * TT];   // 0..31 row-slots (j*4+wn), 32..47 col-slots (32+i*2+wm)
__device__ float g_pos[BB * TT];       // sim[t, t+1]
__device__ float g_part[64];           // per-block partial losses
__device__ unsigned int g_count;       // arrival counter (reset each launch)

// Symmetric 128x128 tile schedule: 36 tiles/batch. code = i | (j<<4) | (full<<8)
__constant__ int c_tiles[36] = {
    0x000, 0x011, 0x022, 0x033, 0x044, 0x055, 0x066, 0x077,   // diagonal
    0x110,
    0x120, 0x121,
    0x130, 0x131, 0x132,
    0x140, 0x141, 0x142, 0x143,
    0x150, 0x151, 0x152, 0x153, 0x154,
    0x160, 0x161, 0x162, 0x163, 0x164, 0x165,
    0x170, 0x171, 0x172, 0x173, 0x174, 0x175, 0x176
};

// ---------------- PTX helpers ----------------------------------------------
__device__ __forceinline__ uint32_t smem_u32(const void* p) {
    uint32_t a;
    asm("{ .reg .u64 t; cvta.to.shared.u64 t, %1; cvt.u32.u64 %0, t; }"
        : "=r"(a) : "l"(p));
    return a;
}
__device__ __forceinline__ void cp16(uint32_t dst, const void* src) {
    asm volatile("cp.async.cg.shared.global [%0], [%1], 16;"
                 :: "r"(dst), "l"(src) : "memory");
}
__device__ __forceinline__ void ldsm4(uint32_t r[4], uint32_t addr) {
    asm volatile("ldmatrix.sync.aligned.m8n8.x4.shared.b16 {%0,%1,%2,%3}, [%4];"
                 : "=r"(r[0]), "=r"(r[1]), "=r"(r[2]), "=r"(r[3]) : "r"(addr));
}
__device__ __forceinline__ void mma_bf16(float c[4], uint32_t a0, uint32_t a1,
                                         uint32_t a2, uint32_t a3,
                                         uint32_t b0, uint32_t b1) {
    asm volatile(
        "mma.sync.aligned.m16n8k16.row.col.f32.bf16.bf16.f32 "
        "{%0,%1,%2,%3}, {%4,%5,%6,%7}, {%8,%9}, {%0,%1,%2,%3};"
        : "+f"(c[0]), "+f"(c[1]), "+f"(c[2]), "+f"(c[3])
        : "r"(a0), "r"(a1), "r"(a2), "r"(a3), "r"(b0), "r"(b1));
}

#define STAGE_BYTES 16384           // A: 128*64B + B: 128*64B
#define NSTAGE 4
#define NCHUNK (DD / 32)            // 16
// conflict-free swizzle: quad(row) = ((row&1)<<2) | (g ^ ((row>>1)&3))
#define SWZ(g, row) (((g) ^ (((row) >> 1) & 3)) * 16)

// ---------------------------------------------------------------------------
// Kernel 1: normalize, emit bf16. Two rows per warp, streaming cache hints.
// ---------------------------------------------------------------------------
__global__ __launch_bounds__(256) void norm_kernel(const float* __restrict__ f) {
    int warp = threadIdx.x >> 5, lane = threadIdx.x & 31;
    int row0 = (blockIdx.x * 8 + warp) * 2;
    float4 v[2][4];
    float ss0 = 0.f, ss1 = 0.f;
#pragma unroll
    for (int q = 0; q < 4; q++) {
        v[0][q] = __ldcs(reinterpret_cast<const float4*>(f + (size_t)row0 * DD) + lane + q * 32);
        v[1][q] = __ldcs(reinterpret_cast<const float4*>(f + (size_t)(row0 + 1) * DD) + lane + q * 32);
        ss0 += v[0][q].x * v[0][q].x + v[0][q].y * v[0][q].y
             + v[0][q].z * v[0][q].z + v[0][q].w * v[0][q].w;
        ss1 += v[1][q].x * v[1][q].x + v[1][q].y * v[1][q].y
             + v[1][q].z * v[1][q].z + v[1][q].w * v[1][q].w;
    }
#pragma unroll
    for (int o = 16; o; o >>= 1) {
        ss0 += __shfl_xor_sync(0xffffffffu, ss0, o);
        ss1 += __shfl_xor_sync(0xffffffffu, ss1, o);
    }
    float inv0 = 1.0f / fmaxf(sqrtf(ss0), 1e-8f);
    float inv1 = 1.0f / fmaxf(sqrtf(ss1), 1e-8f);
#pragma unroll
    for (int rr = 0; rr < 2; rr++) {
        float inv = rr ? inv1 : inv0;
#pragma unroll
        for (int q = 0; q < 4; q++) {
            float n[4] = {v[rr][q].x * inv, v[rr][q].y * inv,
                          v[rr][q].z * inv, v[rr][q].w * inv};
            union { __nv_bfloat16 h[4]; uint2 u; } p;
#pragma unroll
            for (int k = 0; k < 4; k++) p.h[k] = __float2bfloat16(n[k]);
            __stcs(reinterpret_cast<uint2*>(
                       &g_bf[(size_t)(row0 + rr) * DD + (lane + q * 32) * 4]), p.u);
        }
    }
}

// ---------------------------------------------------------------------------
// Kernel 2: bf16 HMMA Gram, 128x128 symmetric tiles + fused exp epilogue.
// 8 warps as 2(M) x 4(N), warp tile 64x32.  (R12 proven config)
// ---------------------------------------------------------------------------
__global__ __launch_bounds__(256, 1) void gram_kernel() {
    extern __shared__ __align__(1024) char smem[];
    const uint32_t sbase = smem_u32(smem);
    const int tid = threadIdx.x;
    const int wid = tid >> 5, lane = tid & 31;
    const int warp_m = wid >> 2, warp_n = wid & 3;

    const int code = c_tiles[blockIdx.x];
    const int ti = code & 15;            // row block
    const int tj = (code >> 4) & 15;     // col block
    const int is_full = code >> 8;       // 1 = strictly above diagonal
    const int t0 = ti * 128;
    const int s0 = tj * 128;
    const int b  = blockIdx.y;
    const __nv_bfloat16* __restrict__ G = g_bf + (size_t)b * TT * DD;

    // ---- load-side per-thread slots (16B each): 2 A + 2 B ----
    const char* asrc[2]; uint32_t adst[2];
    const char* bsrc[2]; uint32_t bdst[2];
#pragma unroll
    for (int i = 0; i < 2; i++) {
        int slot = tid + i * 256, row = slot >> 2, g = slot & 3;
        asrc[i] = reinterpret_cast<const char*>(G + (size_t)(t0 + row) * DD) + g * 16;
        adst[i] = row * 64 + SWZ(g, row);
        bsrc[i] = reinterpret_cast<const char*>(G + (size_t)(s0 + row) * DD) + g * 16;
        bdst[i] = 8192 + row * 64 + SWZ(g, row);
    }

    // ---- ldmatrix per-lane offsets ----
    const int a_row = warp_m * 64 + (lane & 15);
    const int ha = lane >> 4;
    uint32_t a_off[2];
#pragma unroll
    for (int ks = 0; ks < 2; ks++)
        a_off[ks] = a_row * 64 + SWZ(ks * 2 + ha, a_row);
    const int n_row = warp_n * 32 + (lane & 7) + ((lane >> 4) << 3);
    const int hb = (lane >> 3) & 1;
    uint32_t b_off[2];
#pragma unroll
    for (int ks = 0; ks < 2; ks++)
        b_off[ks] = 8192 + n_row * 64 + SWZ(ks * 2 + hb, n_row);

    float acc[4][4][4];
#pragma unroll
    for (int mi = 0; mi < 4; mi++)
#pragma unroll
        for (int ni = 0; ni < 4; ni++)
#pragma unroll
            for (int r = 0; r < 4; r++) acc[mi][ni][r] = 0.f;

#define PREFETCH(c) do {                                                \
        uint32_t st_ = sbase + ((c) & (NSTAGE - 1)) * STAGE_BYTES;      \
        size_t ko_ = (size_t)(c) * 64;                                  \
        cp16(st_ + adst[0], asrc[0] + ko_);                             \
        cp16(st_ + adst[1], asrc[1] + ko_);                             \
        cp16(st_ + bdst[0], bsrc[0] + ko_);                             \
        cp16(st_ + bdst[1], bsrc[1] + ko_);                             \
        asm volatile("cp.async.commit_group;" ::: "memory");            \
    } while (0)

    PREFETCH(0);
    PREFETCH(1);
    PREFETCH(2);

#pragma unroll 1
    for (int c = 0; c < NCHUNK; ++c) {
        if (c + 3 <= NCHUNK)
            asm volatile("cp.async.wait_group 2;" ::: "memory");
        else if (c + 2 == NCHUNK)
            asm volatile("cp.async.wait_group 1;" ::: "memory");
        else
            asm volatile("cp.async.wait_group 0;" ::: "memory");
        __syncthreads();

        if (c + 3 < NCHUNK) PREFETCH(c + 3);

        const uint32_t st = sbase + (c & (NSTAGE - 1)) * STAGE_BYTES;
        uint32_t afr[2][4][4], bfr[2][2][4];
#pragma unroll
        for (int ks = 0; ks < 2; ks++) {
#pragma unroll
            for (int mi = 0; mi < 4; mi++) ldsm4(afr[ks][mi], st + a_off[ks] + mi * 1024);
#pragma unroll
            for (int pi = 0; pi < 2; pi++) ldsm4(bfr[ks][pi], st + b_off[ks] + pi * 1024);
        }
#pragma unroll
        for (int ks = 0; ks < 2; ks++)
#pragma unroll
            for (int mi = 0; mi < 4; mi++)
#pragma unroll
                for (int ni = 0; ni < 4; ni++)
                    mma_bf16(acc[mi][ni],
                             afr[ks][mi][0], afr[ks][mi][1],
                             afr[ks][mi][2], afr[ks][mi][3],
                             bfr[ks][ni >> 1][(ni & 1) * 2],
                             bfr[ks][ni >> 1][(ni & 1) * 2 + 1]);
    }

    // ---- epilogue: exp((cos-1)/T), mask |s-t|<=1; row sums (+ col sums) ----
    const int rL = lane >> 2, cL = (lane & 3) * 2;
    const int row_base = t0 + warp_m * 64;
    const int col_base = s0 + warp_n * 32;
    const int posbase = b * TT;
    float rsum[4][2];
    float csum[4][2];
#pragma unroll
    for (int mi = 0; mi < 4; mi++) { rsum[mi][0] = 0.f; rsum[mi][1] = 0.f; }
#pragma unroll
    for (int ni = 0; ni < 4; ni++) { csum[ni][0] = 0.f; csum[ni][1] = 0.f; }

#pragma unroll
    for (int mi = 0; mi < 4; mi++)
#pragma unroll
        for (int ni = 0; ni < 4; ni++)
#pragma unroll
            for (int r = 0; r < 4; r++) {
                int t = row_base + mi * 16 + rL + (r >> 1) * 8;
                int s = col_base + ni * 8 + cL + (r & 1);
                float v = acc[mi][ni][r];
                int dd = s - t;
                if (dd == 1) g_pos[posbase + t] = v * 14.2857143f;
                float z = fmaf(v, 20.6099291f, -20.6099291f);  // (cos-1)*log2e/T
                float e;
                asm("ex2.approx.ftz.f32 %0, %1;" : "=f"(e) : "f"(z));
                bool keep = (unsigned)(dd + 1) > 2u;
                float em = keep ? e : 0.f;
                rsum[mi][r >> 1] += em;
                csum[ni][r & 1]  += em;
            }

    // row sums: reduce over the 4 lanes sharing each row (lane bits 0,1)
    const int rslot = tj * 4 + warp_n;
#pragma unroll
    for (int mi = 0; mi < 4; mi++)
#pragma unroll
        for (int h = 0; h < 2; h++) {
            float x = rsum[mi][h];
            x += __shfl_xor_sync(0xffffffffu, x, 1);
            x += __shfl_xor_sync(0xffffffffu, x, 2);
            if ((lane & 3) == 0)
                g_S48[rslot][posbase + row_base + mi * 16 + rL + h * 8] = x;
        }

    // col sums (mirror), full tiles only: reduce over lane bits 2,3,4 (rows)
    if (is_full) {
        const int cslot = 32 + ti * 2 + warp_m;
#pragma unroll
        for (int ni = 0; ni < 4; ni++)
#pragma unroll
            for (int p = 0; p < 2; p++) {
                float x = csum[ni][p];
                x += __shfl_xor_sync(0xffffffffu, x, 4);
                x += __shfl_xor_sync(0xffffffffu, x, 8);
                x += __shfl_xor_sync(0xffffffffu, x, 16);
                if ((lane & 28) == 0)
                    g_S48[cslot][posbase + col_base + ni * 8 + (lane & 3) * 2 + p] = x;
            }
    }
}

// ---------------------------------------------------------------------------
// Kernel 3: per-anchor loss (64 blocks) + last-arriving block reduces all
// partials in fixed order (deterministic) and resets the counter.
// ---------------------------------------------------------------------------
__global__ __launch_bounds__(256) void loss_kernel(float* __restrict__ out) {
    const float M = 14.285714285714286f;   // 1/0.07
    int tid = threadIdx.x;
    int idx = blockIdx.x * 256 + tid;      // one anchor per thread
    float acc = 0.f;
    int tt = idx & (TT - 1);
    if (tt != 0 && tt != TT - 1) {
        float S = 0.f;
#pragma unroll
        for (int p = 0; p < 48; p++) S += g_S48[p][idx];
        float pos = g_pos[idx];
        acc = logf(expf(pos - M) + S) + M - pos;
    }
    __shared__ float sm[256];
    sm[tid] = acc;
    __syncthreads();
    for (int o = 128; o; o >>= 1) {
        if (tid < o) sm[tid] += sm[tid + o];
        __syncthreads();
    }
    __shared__ unsigned int rank;
    if (tid == 0) {
        g_part[blockIdx.x] = sm[0];
        __threadfence();
        rank = atomicAdd(&g_count, 1u);
    }
    __syncthreads();
    if (rank == 63) {                      // all 64 partials are visible
        float x = (tid < 64) ? __ldcg(&g_part[tid]) : 0.f;
        sm[tid] = x;
        __syncthreads();
        for (int o = 32; o; o >>= 1) {     // tid<64 active region
            if (tid < o) sm[tid] += sm[tid + o];
            __syncthreads();
        }
        if (tid == 0) {
            out[0] = sm[0] / (float)(BB * (TT - 2));
            g_count = 0;                   // reset for next graph replay
        }
    }
}

// ---------------------------------------------------------------------------
extern "C" void kernel_launch(void* const* d_in, const int* in_sizes, int n_in,
                              void* d_out, int out_size) {
    const float* features = (const float*)d_in[0];
    float* out = (float*)d_out;

    cudaFuncSetAttribute(gram_kernel,
                         cudaFuncAttributeMaxDynamicSharedMemorySize,
                         NSTAGE * STAGE_BYTES);

    norm_kernel<<<BB * TT / 16, 256>>>(features);
    gram_kernel<<<dim3(36, BB), 256, NSTAGE * STAGE_BYTES>>>();
    loss_kernel<<<64, 256>>>(out);
}